// round 1
// baseline (speedup 1.0000x reference)
#include <cuda_runtime.h>
#include <cstdint>

#define C_IN    128
#define C_OUT   64
#define KOFF    27
#define M_PAIRS 100000
#define N_OUTP  200000
#define BN_EPS  1e-5f

// ---------------- scratch (allocation-free: __device__ globals) -------------
__device__ float g_sum[C_OUT];
__device__ float g_sumsq[C_OUT];
__device__ float g_scale[C_OUT];
__device__ float g_bias[C_OUT];

// ---------------- zero stats ------------------------------------------------
__global__ void zero_stats_kernel() {
    int t = threadIdx.x;
    if (t < C_OUT) { g_sum[t] = 0.f; g_sumsq[t] = 0.f; }
}

// ---------------- main conv: gather -> FMA -> scatter-add -------------------
// block: 256 threads (8 warps). blockIdx.y = kernel offset k.
// Each warp handles GROUPS groups of 8 pairs. Lane owns output channels
// {2*lane, 2*lane+1}. x rows held in registers, broadcast via shfl so the
// smem crossbar only serves the weight LDS.64.
constexpr int WARPS  = 8;
constexpr int GROUPS = 8;                       // 8 pairs * 8 groups = 64 pairs/warp
constexpr int PAIRS_PER_BLOCK = WARPS * 8 * GROUPS;   // 512

__global__ void __launch_bounds__(256)
conv_kernel(const float* __restrict__ x,
            const float* __restrict__ w,
            const int*   __restrict__ in_map,
            const int*   __restrict__ out_map,
            float*       __restrict__ out)
{
    __shared__ float ws[C_IN * C_OUT];          // 32 KB
    const int k = blockIdx.y;

    // stage weight[k] into smem (coalesced float4)
    {
        const float4* wk = (const float4*)(w + (size_t)k * C_IN * C_OUT);
        float4* wsv = (float4*)ws;
        #pragma unroll
        for (int i = threadIdx.x; i < C_IN * C_OUT / 4; i += 256)
            wsv[i] = wk[i];
    }
    __syncthreads();

    const int warp = threadIdx.x >> 5;
    const int lane = threadIdx.x & 31;
    const int base0 = blockIdx.x * PAIRS_PER_BLOCK + warp * (8 * GROUPS);
    const int* __restrict__ imk = in_map  + (size_t)k * M_PAIRS;
    const int* __restrict__ omk = out_map + (size_t)k * M_PAIRS;

    for (int g = 0; g < GROUPS; ++g) {
        const int base = base0 + g * 8;
        if (base >= M_PAIRS) break;

        // lanes 0..7 fetch this group's pair indices
        int im = 0, om = 0, lv = 0;
        if (lane < 8) {
            int p = base + lane;
            lv = (p < M_PAIRS);
            if (!lv) p = M_PAIRS - 1;           // clamp: loads stay in bounds
            im = imk[p];
            om = omk[p];
        }

        // gather 8 x-rows into registers (4 regs per row per lane)
        float xr[8][4];
        #pragma unroll
        for (int p = 0; p < 8; ++p) {
            int row = __shfl_sync(0xffffffffu, im, p);
            const float* xrow = x + (size_t)row * C_IN;
            xr[p][0] = xrow[lane];
            xr[p][1] = xrow[lane + 32];
            xr[p][2] = xrow[lane + 64];
            xr[p][3] = xrow[lane + 96];
        }

        float2 acc[8];
        #pragma unroll
        for (int p = 0; p < 8; ++p) acc[p] = make_float2(0.f, 0.f);

        // inner product over c_in: x broadcast by shfl, weight from smem
        #pragma unroll
        for (int j = 0; j < 4; ++j) {
            #pragma unroll 8
            for (int s = 0; s < 32; ++s) {
                const int ci = j * 32 + s;
                const float2 w2 = *(const float2*)&ws[ci * C_OUT + 2 * lane];
                #pragma unroll
                for (int p = 0; p < 8; ++p) {
                    const float xv = __shfl_sync(0xffffffffu, xr[p][j], s);
                    acc[p].x = fmaf(xv, w2.x, acc[p].x);
                    acc[p].y = fmaf(xv, w2.y, acc[p].y);
                }
            }
        }

        // scatter-add: vectorized reduction, no return (RED.64)
        #pragma unroll
        for (int p = 0; p < 8; ++p) {
            const int orow  = __shfl_sync(0xffffffffu, om, p);
            const int valid = __shfl_sync(0xffffffffu, lv, p);
            if (valid) {
                float* dst = out + (size_t)orow * C_OUT + 2 * lane;
                asm volatile("red.global.add.v2.f32 [%0], {%1, %2};"
                             :: "l"(dst), "f"(acc[p].x), "f"(acc[p].y)
                             : "memory");
            }
        }
    }
}

// ---------------- BN stats: per-channel sum / sumsq -------------------------
__global__ void __launch_bounds__(256)
stats_kernel(const float* __restrict__ out)
{
    __shared__ float ss[256], sq[256];
    const int t   = threadIdx.x;
    const int ch  = t & 63;
    const int rep = t >> 6;                      // 4 row-replicas per block
    float s = 0.f, q = 0.f;
    for (int row = blockIdx.x * 4 + rep; row < N_OUTP; row += gridDim.x * 4) {
        const float v = out[(size_t)row * C_OUT + ch];
        s += v;
        q = fmaf(v, v, q);
    }
    ss[t] = s; sq[t] = q;
    __syncthreads();
    if (t < 64) {
        float ts = ss[t] + ss[t + 64] + ss[t + 128] + ss[t + 192];
        float tq = sq[t] + sq[t + 64] + sq[t + 128] + sq[t + 192];
        atomicAdd(&g_sum[t],   ts);
        atomicAdd(&g_sumsq[t], tq);
    }
}

// ---------------- finalize scale/bias ---------------------------------------
__global__ void finalize_kernel(const float* __restrict__ gamma,
                                const float* __restrict__ beta)
{
    const int c = threadIdx.x;
    if (c < C_OUT) {
        const float inv_n = 1.0f / (float)N_OUTP;
        const float mean  = g_sum[c] * inv_n;
        const float var   = g_sumsq[c] * inv_n - mean * mean;
        const float sc    = gamma[c] * rsqrtf(var + BN_EPS);
        g_scale[c] = sc;
        g_bias[c]  = beta[c] - mean * sc;
    }
}

// ---------------- normalize + ReLU (in place, float4) -----------------------
__global__ void __launch_bounds__(256)
normalize_kernel(float* __restrict__ out)
{
    __shared__ float sc[C_OUT], bs[C_OUT];
    if (threadIdx.x < C_OUT) {
        sc[threadIdx.x] = g_scale[threadIdx.x];
        bs[threadIdx.x] = g_bias[threadIdx.x];
    }
    __syncthreads();

    const int total4 = N_OUTP * C_OUT / 4;
    for (int i = blockIdx.x * blockDim.x + threadIdx.x; i < total4;
         i += gridDim.x * blockDim.x) {
        float4 v = ((float4*)out)[i];
        const int c0 = (i * 4) & 63;
        v.x = fmaxf(fmaf(v.x, sc[c0 + 0], bs[c0 + 0]), 0.f);
        v.y = fmaxf(fmaf(v.y, sc[c0 + 1], bs[c0 + 1]), 0.f);
        v.z = fmaxf(fmaf(v.z, sc[c0 + 2], bs[c0 + 2]), 0.f);
        v.w = fmaxf(fmaf(v.w, sc[c0 + 3], bs[c0 + 3]), 0.f);
        ((float4*)out)[i] = v;
    }
}

// ---------------- launch ----------------------------------------------------
extern "C" void kernel_launch(void* const* d_in, const int* in_sizes, int n_in,
                              void* d_out, int out_size)
{
    const float* x       = (const float*)d_in[0];
    const float* weight  = (const float*)d_in[1];
    const float* gamma   = (const float*)d_in[2];
    const float* beta    = (const float*)d_in[3];
    const int*   in_map  = (const int*)d_in[4];
    const int*   out_map = (const int*)d_in[5];
    float*       out     = (float*)d_out;

    // 1) zero accumulator + stats
    cudaMemsetAsync(out, 0, (size_t)out_size * sizeof(float));
    zero_stats_kernel<<<1, 128>>>();

    // 2) fused gather-GEMM-scatter over 27 kernel offsets
    {
        dim3 grid((M_PAIRS + PAIRS_PER_BLOCK - 1) / PAIRS_PER_BLOCK, KOFF);
        conv_kernel<<<grid, 256>>>(x, weight, in_map, out_map, out);
    }

    // 3) BN statistics
    stats_kernel<<<296, 256>>>(out);

    // 4) scale/bias
    finalize_kernel<<<1, 64>>>(gamma, beta);

    // 5) normalize + ReLU
    normalize_kernel<<<2048, 256>>>(out);
}

// round 3
// speedup vs baseline: 2.4179x; 2.4179x over previous
#include <cuda_runtime.h>
#include <cuda_fp16.h>
#include <cstdint>

#define C_IN    128
#define C_OUT   64
#define KOFF    27
#define M_PAIRS 100000
#define N_ROWS  100000
#define N_OUTP  200000
#define BN_EPS  1e-5f

// ---------------- device scratch (allocation-free) --------------------------
__device__ __half g_Xh[(size_t)N_ROWS * C_IN];      // 25.6 MB, L2-resident
__device__ __half g_Wh[(size_t)KOFF * C_OUT * C_IN];// [k][co][ci], 0.44 MB
__device__ float g_sum[C_OUT], g_sumsq[C_OUT], g_scale[C_OUT], g_bias[C_OUT];

// ---------------- PTX helpers ----------------------------------------------
__device__ __forceinline__ uint32_t smem_u32(const void* p) {
    uint32_t a;
    asm("{ .reg .u64 t; cvta.to.shared.u64 t, %1; cvt.u32.u64 %0, t; }" : "=r"(a) : "l"(p));
    return a;
}
#define CP_ASYNC16(dst, src) \
    asm volatile("cp.async.cg.shared.global [%0], [%1], 16;" :: "r"(dst), "l"(src))
#define CP_COMMIT() asm volatile("cp.async.commit_group;")
#define CP_WAIT0()  asm volatile("cp.async.wait_group 0;" ::: "memory")

#define LDMATRIX_X4(r, addr) \
    asm volatile("ldmatrix.sync.aligned.m8n8.x4.shared.b16 {%0,%1,%2,%3}, [%4];" \
        : "=r"((r)[0]), "=r"((r)[1]), "=r"((r)[2]), "=r"((r)[3]) : "r"(addr))

#define MMA16816(d, a, b0, b1) \
    asm volatile("mma.sync.aligned.m16n8k16.row.col.f32.f16.f16.f32 " \
        "{%0,%1,%2,%3}, {%4,%5,%6,%7}, {%8,%9}, {%0,%1,%2,%3};" \
        : "+f"((d)[0]), "+f"((d)[1]), "+f"((d)[2]), "+f"((d)[3]) \
        : "r"((a)[0]), "r"((a)[1]), "r"((a)[2]), "r"((a)[3]), "r"(b0), "r"(b1))

// ---------------- convert x -> fp16 -----------------------------------------
__global__ void __launch_bounds__(256)
conv_x_kernel(const float* __restrict__ x)
{
    int idx = blockIdx.x * 256 + threadIdx.x;          // one per 4 floats
    if (idx >= N_ROWS * 32) return;
    float4 v = ((const float4*)x)[idx];
    __half2* dst = (__half2*)(g_Xh + (size_t)idx * 4);
    dst[0] = __floats2half2_rn(v.x, v.y);
    dst[1] = __floats2half2_rn(v.z, v.w);
}

// ---------------- convert w -> fp16, transpose to [k][co][ci] ---------------
__global__ void __launch_bounds__(256)
conv_w_kernel(const float* __restrict__ w)
{
    int idx = blockIdx.x * 256 + threadIdx.x;          // over 27*128*64
    if (idx >= KOFF * C_IN * C_OUT) return;
    int k  = idx / (C_IN * C_OUT);
    int r  = idx % (C_IN * C_OUT);
    int ci = r / C_OUT, co = r % C_OUT;
    g_Wh[(size_t)k * (C_OUT * C_IN) + co * C_IN + ci] = __float2half_rn(w[idx]);
}

// ---------------- fused gather + HMMA GEMM + scatter-add --------------------
// grid = (782 pair-blocks, 27 offsets); block = 128 threads (4 warps).
// Per block: tile = 128 pairs x 64 out-channels, K = 128.
// smem: As 128x128 fp16 (32KB, XOR-swizzled) | Bs 64x128 fp16 (16KB) | som 512B
// stage (128x64 f32, 32KB) reuses As after the MMA loop.
#define SMEM_FUSED (49152 + 512)

__global__ void __launch_bounds__(128)
fused_kernel(const int* __restrict__ in_map,
             const int* __restrict__ out_map,
             float* __restrict__ out)
{
    extern __shared__ char smem[];
    const uint32_t sbase = smem_u32(smem);
    const uint32_t bbase = sbase + 32768;
    int* som = (int*)(smem + 49152);

    const int t    = threadIdx.x;
    const int lane = t & 31;
    const int w    = t >> 5;
    const int k    = blockIdx.y;

    // ---- pair indices (thread t owns pair-row t) ----
    const int p     = blockIdx.x * 128 + t;
    const int valid = (p < M_PAIRS);
    const int pc    = valid ? p : (M_PAIRS - 1);
    const int im    = in_map [k * M_PAIRS + pc];
    const int om    = out_map[k * M_PAIRS + pc];
    som[t] = valid ? om : -1;

    // ---- gather A: row t = x row im (16 x 16B, swizzle chunk ^= row&7) ----
    {
        const __half* src = g_Xh + (size_t)im * C_IN;
        const uint32_t arow = sbase + t * 256;
        #pragma unroll
        for (int c = 0; c < 16; ++c)
            CP_ASYNC16(arow + (((c ^ (t & 7)) << 4)), src + c * 8);
    }
    // ---- load B: w[k] as [co][ci], 64 rows x 16 chunks ----
    {
        const __half* src0 = g_Wh + (size_t)k * (C_OUT * C_IN);
        #pragma unroll
        for (int j = 0; j < 8; ++j) {
            int ci_  = t + j * 128;
            int rowb = ci_ >> 4, ch = ci_ & 15;
            CP_ASYNC16(bbase + rowb * 256 + ((ch ^ (rowb & 7)) << 4),
                       src0 + rowb * C_IN + ch * 8);
        }
    }
    CP_COMMIT(); CP_WAIT0();
    __syncthreads();

    // ---- MMA mainloop: warp w owns rows [32w, 32w+32), cols 0..63 ----
    float d[2][8][4];
    #pragma unroll
    for (int mt = 0; mt < 2; ++mt)
        #pragma unroll
        for (int nt = 0; nt < 8; ++nt)
            #pragma unroll
            for (int j = 0; j < 4; ++j) d[mt][nt][j] = 0.f;

    #pragma unroll
    for (int kc = 0; kc < 8; ++kc) {
        uint32_t a_frag[2][4];
        #pragma unroll
        for (int mt = 0; mt < 2; ++mt) {
            int row = w * 32 + mt * 16 + (lane & 15);
            int ch  = kc * 2 + (lane >> 4);
            LDMATRIX_X4(a_frag[mt], sbase + row * 256 + ((ch ^ (row & 7)) << 4));
        }
        uint32_t b_frag[4][4];
        #pragma unroll
        for (int nt2 = 0; nt2 < 4; ++nt2) {
            int n  = nt2 * 16 + ((lane >> 4) << 3) + (lane & 7);
            int ch = kc * 2 + ((lane >> 3) & 1);
            LDMATRIX_X4(b_frag[nt2], bbase + n * 256 + ((ch ^ (n & 7)) << 4));
        }
        #pragma unroll
        for (int mt = 0; mt < 2; ++mt)
            #pragma unroll
            for (int nt = 0; nt < 8; ++nt)
                MMA16816(d[mt][nt], a_frag[mt],
                         b_frag[nt >> 1][(nt & 1) * 2],
                         b_frag[nt >> 1][(nt & 1) * 2 + 1]);
    }

    // ---- stage accumulators to smem (reuse As region) ----
    __syncthreads();                       // all ldmatrix reads done
    float* stage = (float*)smem;           // 128 x 64 f32
    #pragma unroll
    for (int mt = 0; mt < 2; ++mt) {
        #pragma unroll
        for (int nt = 0; nt < 8; ++nt) {
            int row = w * 32 + mt * 16 + (lane >> 2);
            int col = nt * 8 + (lane & 3) * 2;
            *(float2*)&stage[row * 64 + col]       = make_float2(d[mt][nt][0], d[mt][nt][1]);
            *(float2*)&stage[(row + 8) * 64 + col] = make_float2(d[mt][nt][2], d[mt][nt][3]);
        }
    }
    __syncthreads();

    // ---- scatter-add: thread t scatters pair-row t (16 x red.v4) ----
    const int omr = som[t];
    if (omr >= 0) {
        const float4* src = (const float4*)(stage + t * 64);
        float* dst = out + (size_t)omr * C_OUT;
        #pragma unroll
        for (int c4 = 0; c4 < 16; ++c4) {
            float4 v = src[c4];
            asm volatile("red.global.add.v4.f32 [%0], {%1,%2,%3,%4};"
                         :: "l"(dst + c4 * 4), "f"(v.x), "f"(v.y), "f"(v.z), "f"(v.w)
                         : "memory");
        }
    }
}

// ---------------- BN ---------------------------------------------------------
__global__ void zero_stats_kernel() {
    int t = threadIdx.x;
    if (t < C_OUT) { g_sum[t] = 0.f; g_sumsq[t] = 0.f; }
}

__global__ void __launch_bounds__(256)
stats_kernel(const float* __restrict__ out)
{
    __shared__ float ss[256], sq[256];
    const int t = threadIdx.x, ch = t & 63, rep = t >> 6;
    float s = 0.f, q = 0.f;
    for (int row = blockIdx.x * 4 + rep; row < N_OUTP; row += gridDim.x * 4) {
        const float v = out[(size_t)row * C_OUT + ch];
        s += v; q = fmaf(v, v, q);
    }
    ss[t] = s; sq[t] = q;
    __syncthreads();
    if (t < 64) {
        atomicAdd(&g_sum[t],   ss[t] + ss[t + 64] + ss[t + 128] + ss[t + 192]);
        atomicAdd(&g_sumsq[t], sq[t] + sq[t + 64] + sq[t + 128] + sq[t + 192]);
    }
}

__global__ void finalize_kernel(const float* __restrict__ gamma,
                                const float* __restrict__ beta)
{
    const int c = threadIdx.x;
    if (c < C_OUT) {
        const float inv_n = 1.0f / (float)N_OUTP;
        const float mean = g_sum[c] * inv_n;
        const float var  = g_sumsq[c] * inv_n - mean * mean;
        const float sc   = gamma[c] * rsqrtf(var + BN_EPS);
        g_scale[c] = sc;
        g_bias[c]  = beta[c] - mean * sc;
    }
}

__global__ void __launch_bounds__(256)
normalize_kernel(float* __restrict__ out)
{
    __shared__ float sc[C_OUT], bs[C_OUT];
    if (threadIdx.x < C_OUT) {
        sc[threadIdx.x] = g_scale[threadIdx.x];
        bs[threadIdx.x] = g_bias[threadIdx.x];
    }
    __syncthreads();
    const int total4 = N_OUTP * C_OUT / 4;
    for (int i = blockIdx.x * blockDim.x + threadIdx.x; i < total4;
         i += gridDim.x * blockDim.x) {
        float4 v = ((float4*)out)[i];
        const int c0 = (i * 4) & 63;
        v.x = fmaxf(fmaf(v.x, sc[c0 + 0], bs[c0 + 0]), 0.f);
        v.y = fmaxf(fmaf(v.y, sc[c0 + 1], bs[c0 + 1]), 0.f);
        v.z = fmaxf(fmaf(v.z, sc[c0 + 2], bs[c0 + 2]), 0.f);
        v.w = fmaxf(fmaf(v.w, sc[c0 + 3], bs[c0 + 3]), 0.f);
        ((float4*)out)[i] = v;
    }
}

// ---------------- launch ----------------------------------------------------
extern "C" void kernel_launch(void* const* d_in, const int* in_sizes, int n_in,
                              void* d_out, int out_size)
{
    const float* x       = (const float*)d_in[0];
    const float* weight  = (const float*)d_in[1];
    const float* gamma   = (const float*)d_in[2];
    const float* beta    = (const float*)d_in[3];
    const int*   in_map  = (const int*)d_in[4];
    const int*   out_map = (const int*)d_in[5];
    float*       out     = (float*)d_out;

    cudaFuncSetAttribute(fused_kernel, cudaFuncAttributeMaxDynamicSharedMemorySize,
                         SMEM_FUSED);

    cudaMemsetAsync(out, 0, (size_t)out_size * sizeof(float));
    zero_stats_kernel<<<1, 128>>>();

    conv_x_kernel<<<(N_ROWS * 32 + 255) / 256, 256>>>(x);
    conv_w_kernel<<<(KOFF * C_IN * C_OUT + 255) / 256, 256>>>(weight);

    {
        dim3 grid((M_PAIRS + 127) / 128, KOFF);
        fused_kernel<<<grid, 128, SMEM_FUSED>>>(in_map, out_map, out);
    }

    stats_kernel<<<296, 256>>>(out);
    finalize_kernel<<<1, 64>>>(gamma, beta);
    normalize_kernel<<<2048, 256>>>(out);
}

// round 4
// speedup vs baseline: 4.7661x; 1.9712x over previous
#include <cuda_runtime.h>
#include <cuda_fp16.h>
#include <cstdint>

#define C_IN    128
#define C_OUT   64
#define KOFF    27
#define M_PAIRS 100000
#define N_ROWS  100000
#define N_OUTP  200000
#define BN_EPS  1e-5f

// ---------------- device scratch (allocation-free) --------------------------
__device__ __half g_Xh[(size_t)N_ROWS * C_IN];      // 25.6 MB, L2-resident
__device__ __half g_Wh[(size_t)KOFF * C_OUT * C_IN];// [k][co][ci], 0.44 MB
__device__ float g_sum[C_OUT], g_sumsq[C_OUT], g_scale[C_OUT], g_bias[C_OUT];

// ---------------- PTX helpers ----------------------------------------------
__device__ __forceinline__ uint32_t smem_u32(const void* p) {
    uint32_t a;
    asm("{ .reg .u64 t; cvta.to.shared.u64 t, %1; cvt.u32.u64 %0, t; }" : "=r"(a) : "l"(p));
    return a;
}
#define BULK_CP(dst, src, bytes, mbar) \
    asm volatile("cp.async.bulk.shared::cluster.global.mbarrier::complete_tx::bytes " \
        "[%0], [%1], %2, [%3];" :: "r"(dst), "l"(src), "r"(bytes), "r"(mbar) : "memory")

#define MBAR_INIT(a, c) \
    asm volatile("mbarrier.init.shared.b64 [%0], %1;" :: "r"(a), "r"(c) : "memory")
#define MBAR_EXPECT_TX(a, tx) \
    asm volatile("mbarrier.arrive.expect_tx.shared.b64 _, [%0], %1;" :: "r"(a), "r"(tx) : "memory")
#define MBAR_WAIT(a, ph) do {                                                   \
    asm volatile("{ .reg .pred P; WL%=:"                                        \
        " mbarrier.try_wait.parity.acquire.cta.shared::cta.b64 P, [%0], %1, 0x989680;" \
        " @P bra.uni WD%=; bra.uni WL%=; WD%=: }"                               \
        :: "r"(a), "r"(ph) : "memory");                                         \
} while (0)

#define LDMATRIX_X4(r, addr) \
    asm volatile("ldmatrix.sync.aligned.m8n8.x4.shared.b16 {%0,%1,%2,%3}, [%4];" \
        : "=r"((r)[0]), "=r"((r)[1]), "=r"((r)[2]), "=r"((r)[3]) : "r"(addr))

#define MMA16816(d, a, b0, b1) \
    asm volatile("mma.sync.aligned.m16n8k16.row.col.f32.f16.f16.f32 " \
        "{%0,%1,%2,%3}, {%4,%5,%6,%7}, {%8,%9}, {%0,%1,%2,%3};" \
        : "+f"((d)[0]), "+f"((d)[1]), "+f"((d)[2]), "+f"((d)[3]) \
        : "r"((a)[0]), "r"((a)[1]), "r"((a)[2]), "r"((a)[3]), "r"(b0), "r"(b1))

// ---------------- convert x -> fp16 -----------------------------------------
__global__ void __launch_bounds__(256)
conv_x_kernel(const float* __restrict__ x)
{
    int idx = blockIdx.x * 256 + threadIdx.x;          // one per 4 floats
    if (idx >= N_ROWS * 32) return;
    float4 v = ((const float4*)x)[idx];
    __half2* dst = (__half2*)(g_Xh + (size_t)idx * 4);
    dst[0] = __floats2half2_rn(v.x, v.y);
    dst[1] = __floats2half2_rn(v.z, v.w);
}

// ---------------- convert w -> fp16, transpose to [k][co][ci] ---------------
__global__ void __launch_bounds__(256)
conv_w_kernel(const float* __restrict__ w)
{
    int idx = blockIdx.x * 256 + threadIdx.x;          // over 27*128*64
    if (idx >= KOFF * C_IN * C_OUT) return;
    int k  = idx / (C_IN * C_OUT);
    int r  = idx % (C_IN * C_OUT);
    int ci = r / C_OUT, co = r % C_OUT;
    g_Wh[(size_t)k * (C_OUT * C_IN) + co * C_IN + ci] = __float2half_rn(w[idx]);
}

// ---------------- fused gather(bulk-DMA) + HMMA + direct-frag scatter -------
// grid = (782 pair-blocks, 27 offsets); block = 128 threads (4 warps).
// Tile: 128 pairs x 64 out-channels, K = 128.
// smem rows padded to 272 B -> ldmatrix conflict-free, no swizzle needed.
// layout: [0,8) mbar | [16,528) som | A @544 (128x272) | B @35360 (64x272)
#define ROWB     272
#define SM_MBAR  0
#define SM_SOM   16
#define SM_A     544
#define SM_B     (SM_A + 128 * ROWB)          // 35360
#define SMEM_FUSED (SM_B + 64 * ROWB)         // 52768

__global__ void __launch_bounds__(128)
fused_kernel(const int* __restrict__ in_map,
             const int* __restrict__ out_map,
             float* __restrict__ out)
{
    extern __shared__ char smem[];
    const uint32_t sbase = smem_u32(smem);
    const uint32_t abase = sbase + SM_A;
    const uint32_t bbase = sbase + SM_B;
    int* som = (int*)(smem + SM_SOM);

    const int t    = threadIdx.x;
    const int lane = t & 31;
    const int w    = t >> 5;
    const int k    = blockIdx.y;

    // ---- pair indices (thread t owns pair-row t) ----
    const int p     = blockIdx.x * 128 + t;
    const int valid = (p < M_PAIRS);
    const int pc    = valid ? p : (M_PAIRS - 1);
    const int im    = in_map [k * M_PAIRS + pc];
    const int om    = out_map[k * M_PAIRS + pc];
    som[t] = valid ? om : -1;

    if (t == 0) MBAR_INIT(sbase + SM_MBAR, 1);
    __syncthreads();
    if (t == 0) MBAR_EXPECT_TX(sbase + SM_MBAR, 128 * 256 + 64 * 256);

    // ---- gather A: one 256B bulk per row; B: one per row (threads 0..63) ---
    BULK_CP(abase + t * ROWB, g_Xh + (size_t)im * C_IN, 256, sbase + SM_MBAR);
    if (t < 64)
        BULK_CP(bbase + t * ROWB, g_Wh + ((size_t)k * C_OUT + t) * C_IN, 256,
                sbase + SM_MBAR);

    MBAR_WAIT(sbase + SM_MBAR, 0);
    __syncthreads();

    // ---- MMA mainloop: warp w owns rows [32w, 32w+32), cols 0..63 ----
    float d[2][8][4];
    #pragma unroll
    for (int mt = 0; mt < 2; ++mt)
        #pragma unroll
        for (int nt = 0; nt < 8; ++nt)
            #pragma unroll
            for (int j = 0; j < 4; ++j) d[mt][nt][j] = 0.f;

    #pragma unroll
    for (int kc = 0; kc < 8; ++kc) {
        uint32_t a_frag[2][4];
        #pragma unroll
        for (int mt = 0; mt < 2; ++mt) {
            int row = w * 32 + mt * 16 + (lane & 15);
            int ch  = kc * 2 + (lane >> 4);
            LDMATRIX_X4(a_frag[mt], abase + row * ROWB + ch * 16);
        }
        uint32_t b_frag[4][4];
        #pragma unroll
        for (int nt2 = 0; nt2 < 4; ++nt2) {
            int n  = nt2 * 16 + ((lane >> 4) << 3) + (lane & 7);
            int ch = kc * 2 + ((lane >> 3) & 1);
            LDMATRIX_X4(b_frag[nt2], bbase + n * ROWB + ch * 16);
        }
        #pragma unroll
        for (int mt = 0; mt < 2; ++mt)
            #pragma unroll
            for (int nt = 0; nt < 8; ++nt)
                MMA16816(d[mt][nt], a_frag[mt],
                         b_frag[nt >> 1][(nt & 1) * 2],
                         b_frag[nt >> 1][(nt & 1) * 2 + 1]);
    }

    // ---- scatter-add straight from fragments ----
    // fragment (mt, nt): rows r0 = w*32+mt*16+(lane>>2), r0+8;
    // cols nt*8 + (lane&3)*2 -> 4 lanes cover one 32B sector of one row.
    #pragma unroll
    for (int mt = 0; mt < 2; ++mt) {
        const int r0  = w * 32 + mt * 16 + (lane >> 2);
        const int om0 = som[r0];
        const int om1 = som[r0 + 8];
        float* dst0 = out + (size_t)om0 * C_OUT + (lane & 3) * 2;
        float* dst1 = out + (size_t)om1 * C_OUT + (lane & 3) * 2;
        #pragma unroll
        for (int nt = 0; nt < 8; ++nt) {
            if (om0 >= 0)
                asm volatile("red.global.add.v2.f32 [%0], {%1,%2};"
                             :: "l"(dst0 + nt * 8), "f"(d[mt][nt][0]), "f"(d[mt][nt][1])
                             : "memory");
            if (om1 >= 0)
                asm volatile("red.global.add.v2.f32 [%0], {%1,%2};"
                             :: "l"(dst1 + nt * 8), "f"(d[mt][nt][2]), "f"(d[mt][nt][3])
                             : "memory");
        }
    }
}

// ---------------- BN ---------------------------------------------------------
__global__ void zero_stats_kernel() {
    int t = threadIdx.x;
    if (t < C_OUT) { g_sum[t] = 0.f; g_sumsq[t] = 0.f; }
}

__global__ void __launch_bounds__(256)
stats_kernel(const float* __restrict__ out)
{
    __shared__ float ss[256], sq[256];
    const int t = threadIdx.x, ch = t & 63, rep = t >> 6;
    float s = 0.f, q = 0.f;
    for (int row = blockIdx.x * 4 + rep; row < N_OUTP; row += gridDim.x * 4) {
        const float v = out[(size_t)row * C_OUT + ch];
        s += v; q = fmaf(v, v, q);
    }
    ss[t] = s; sq[t] = q;
    __syncthreads();
    if (t < 64) {
        atomicAdd(&g_sum[t],   ss[t] + ss[t + 64] + ss[t + 128] + ss[t + 192]);
        atomicAdd(&g_sumsq[t], sq[t] + sq[t + 64] + sq[t + 128] + sq[t + 192]);
    }
}

__global__ void finalize_kernel(const float* __restrict__ gamma,
                                const float* __restrict__ beta)
{
    const int c = threadIdx.x;
    if (c < C_OUT) {
        const float inv_n = 1.0f / (float)N_OUTP;
        const float mean = g_sum[c] * inv_n;
        const float var  = g_sumsq[c] * inv_n - mean * mean;
        const float sc   = gamma[c] * rsqrtf(var + BN_EPS);
        g_scale[c] = sc;
        g_bias[c]  = beta[c] - mean * sc;
    }
}

__global__ void __launch_bounds__(256)
normalize_kernel(float* __restrict__ out)
{
    __shared__ float sc[C_OUT], bs[C_OUT];
    if (threadIdx.x < C_OUT) {
        sc[threadIdx.x] = g_scale[threadIdx.x];
        bs[threadIdx.x] = g_bias[threadIdx.x];
    }
    __syncthreads();
    const int total4 = N_OUTP * C_OUT / 4;
    for (int i = blockIdx.x * blockDim.x + threadIdx.x; i < total4;
         i += gridDim.x * blockDim.x) {
        float4 v = ((float4*)out)[i];
        const int c0 = (i * 4) & 63;
        v.x = fmaxf(fmaf(v.x, sc[c0 + 0], bs[c0 + 0]), 0.f);
        v.y = fmaxf(fmaf(v.y, sc[c0 + 1], bs[c0 + 1]), 0.f);
        v.z = fmaxf(fmaf(v.z, sc[c0 + 2], bs[c0 + 2]), 0.f);
        v.w = fmaxf(fmaf(v.w, sc[c0 + 3], bs[c0 + 3]), 0.f);
        ((float4*)out)[i] = v;
    }
}

// ---------------- launch ----------------------------------------------------
extern "C" void kernel_launch(void* const* d_in, const int* in_sizes, int n_in,
                              void* d_out, int out_size)
{
    const float* x       = (const float*)d_in[0];
    const float* weight  = (const float*)d_in[1];
    const float* gamma   = (const float*)d_in[2];
    const float* beta    = (const float*)d_in[3];
    const int*   in_map  = (const int*)d_in[4];
    const int*   out_map = (const int*)d_in[5];
    float*       out     = (float*)d_out;

    cudaFuncSetAttribute(fused_kernel, cudaFuncAttributeMaxDynamicSharedMemorySize,
                         SMEM_FUSED);

    cudaMemsetAsync(out, 0, (size_t)out_size * sizeof(float));
    zero_stats_kernel<<<1, 128>>>();

    conv_x_kernel<<<(N_ROWS * 32 + 255) / 256, 256>>>(x);
    conv_w_kernel<<<(KOFF * C_IN * C_OUT + 255) / 256, 256>>>(weight);

    {
        dim3 grid((M_PAIRS + 127) / 128, KOFF);
        fused_kernel<<<grid, 128, SMEM_FUSED>>>(in_map, out_map, out);
    }

    stats_kernel<<<296, 256>>>(out);
    finalize_kernel<<<1, 64>>>(gamma, beta);
    normalize_kernel<<<2048, 256>>>(out);
}

// round 5
// speedup vs baseline: 5.7127x; 1.1986x over previous
#include <cuda_runtime.h>
#include <cuda_fp16.h>
#include <cstdint>

#define C_IN    128
#define C_OUT   64
#define KOFF    27
#define M_PAIRS 100000
#define N_ROWS  100000
#define N_OUTP  200000
#define BN_EPS  1e-5f

// ---------------- device scratch (allocation-free) --------------------------
__device__ __half g_Xh[(size_t)N_ROWS * C_IN];      // 25.6 MB, L2-resident
__device__ __half g_Wh[(size_t)KOFF * C_OUT * C_IN];// [k][co][ci], 0.44 MB
__device__ float g_sum[C_OUT], g_sumsq[C_OUT], g_scale[C_OUT], g_bias[C_OUT];

// ---------------- PTX helpers ----------------------------------------------
__device__ __forceinline__ uint32_t smem_u32(const void* p) {
    uint32_t a;
    asm("{ .reg .u64 t; cvta.to.shared.u64 t, %1; cvt.u32.u64 %0, t; }" : "=r"(a) : "l"(p));
    return a;
}
#define BULK_CP(dst, src, bytes, mbar) \
    asm volatile("cp.async.bulk.shared::cluster.global.mbarrier::complete_tx::bytes " \
        "[%0], [%1], %2, [%3];" :: "r"(dst), "l"(src), "r"(bytes), "r"(mbar) : "memory")

#define MBAR_INIT(a, c) \
    asm volatile("mbarrier.init.shared.b64 [%0], %1;" :: "r"(a), "r"(c) : "memory")
#define MBAR_EXPECT_TX(a, tx) \
    asm volatile("mbarrier.arrive.expect_tx.shared.b64 _, [%0], %1;" :: "r"(a), "r"(tx) : "memory")
#define MBAR_WAIT(a, ph) do {                                                   \
    asm volatile("{ .reg .pred P; WL%=:"                                        \
        " mbarrier.try_wait.parity.acquire.cta.shared::cta.b64 P, [%0], %1, 0x989680;" \
        " @P bra.uni WD%=; bra.uni WL%=; WD%=: }"                               \
        :: "r"(a), "r"(ph) : "memory");                                         \
} while (0)

#define LDMATRIX_X4(r, addr) \
    asm volatile("ldmatrix.sync.aligned.m8n8.x4.shared.b16 {%0,%1,%2,%3}, [%4];" \
        : "=r"((r)[0]), "=r"((r)[1]), "=r"((r)[2]), "=r"((r)[3]) : "r"(addr))

#define MMA16816(d, a, b0, b1) \
    asm volatile("mma.sync.aligned.m16n8k16.row.col.f32.f16.f16.f32 " \
        "{%0,%1,%2,%3}, {%4,%5,%6,%7}, {%8,%9}, {%0,%1,%2,%3};" \
        : "+f"((d)[0]), "+f"((d)[1]), "+f"((d)[2]), "+f"((d)[3]) \
        : "r"((a)[0]), "r"((a)[1]), "r"((a)[2]), "r"((a)[3]), "r"(b0), "r"(b1))

// ---------------- convert x -> fp16 -----------------------------------------
__global__ void __launch_bounds__(256)
conv_x_kernel(const float* __restrict__ x)
{
    int idx = blockIdx.x * 256 + threadIdx.x;          // one per 4 floats
    if (idx >= N_ROWS * 32) return;
    float4 v = ((const float4*)x)[idx];
    __half2* dst = (__half2*)(g_Xh + (size_t)idx * 4);
    dst[0] = __floats2half2_rn(v.x, v.y);
    dst[1] = __floats2half2_rn(v.z, v.w);
}

// ---------------- convert w -> fp16, transpose to [k][co][ci] ---------------
__global__ void __launch_bounds__(256)
conv_w_kernel(const float* __restrict__ w)
{
    int idx = blockIdx.x * 256 + threadIdx.x;          // over 27*128*64
    if (idx >= KOFF * C_IN * C_OUT) return;
    int k  = idx / (C_IN * C_OUT);
    int r  = idx % (C_IN * C_OUT);
    int ci = r / C_OUT, co = r % C_OUT;
    g_Wh[(size_t)k * (C_OUT * C_IN) + co * C_IN + ci] = __float2half_rn(w[idx]);
}

// ---------------- fused gather(bulk) + HMMA + direct-frag scatter -----------
// grid = (521 pair-blocks, 27 offsets); block = 192 threads (6 warps).
// Tile: 192 pairs x 64 out-channels, K = 128. Warp w owns rows [32w, 32w+32).
// Split barriers: bar0 = A rows 0..95 + B; bar1 = A rows 96..191 ->
// warps 0-2 start MMA while second half of gather is in flight.
// smem rows padded to 272 B -> ldmatrix conflict-free, no swizzle.
#define PAIRS_BLK 192
#define ROWB      272
#define SM_MBAR0  0
#define SM_MBAR1  8
#define SM_A      32
#define SM_B      (SM_A + PAIRS_BLK * ROWB)     // 52256
#define SMEM_FUSED (SM_B + 64 * ROWB)           // 69664

__global__ void __launch_bounds__(PAIRS_BLK)
fused_kernel(const int* __restrict__ in_map,
             const int* __restrict__ out_map,
             float* __restrict__ out)
{
    extern __shared__ char smem[];
    const uint32_t sbase = smem_u32(smem);
    const uint32_t abase = sbase + SM_A;
    const uint32_t bbase = sbase + SM_B;

    const int t    = threadIdx.x;
    const int lane = t & 31;
    const int w    = t >> 5;
    const int k    = blockIdx.y;

    // ---- pair indices (thread t owns pair-row t) ----
    const int p     = blockIdx.x * PAIRS_BLK + t;
    const int valid = (p < M_PAIRS);
    const int pc    = valid ? p : (M_PAIRS - 1);
    const int im    = in_map [k * M_PAIRS + pc];
    const int om    = valid ? out_map[k * M_PAIRS + pc] : -1;

    if (t == 0) { MBAR_INIT(sbase + SM_MBAR0, 1); MBAR_INIT(sbase + SM_MBAR1, 1); }
    __syncthreads();
    if (t == 0) MBAR_EXPECT_TX(sbase + SM_MBAR0, 96 * 256 + 64 * 256);
    if (t == 1) MBAR_EXPECT_TX(sbase + SM_MBAR1, 96 * 256);

    // ---- gather A: one 256B bulk per row; B rows by threads 0..63 ----
    const uint32_t mybar = sbase + (t < 96 ? SM_MBAR0 : SM_MBAR1);
    BULK_CP(abase + t * ROWB, g_Xh + (size_t)im * C_IN, 256, mybar);
    if (t < 64)
        BULK_CP(bbase + t * ROWB, g_Wh + ((size_t)k * C_OUT + t) * C_IN, 256,
                sbase + SM_MBAR0);

    MBAR_WAIT(sbase + SM_MBAR0, 0);
    if (w >= 3) MBAR_WAIT(sbase + SM_MBAR1, 0);

    // ---- MMA mainloop: warp w owns rows [32w, 32w+32), cols 0..63 ----
    float d[2][8][4];
    #pragma unroll
    for (int mt = 0; mt < 2; ++mt)
        #pragma unroll
        for (int nt = 0; nt < 8; ++nt)
            #pragma unroll
            for (int j = 0; j < 4; ++j) d[mt][nt][j] = 0.f;

    #pragma unroll
    for (int kc = 0; kc < 8; ++kc) {
        uint32_t a_frag[2][4];
        #pragma unroll
        for (int mt = 0; mt < 2; ++mt) {
            int row = w * 32 + mt * 16 + (lane & 15);
            int ch  = kc * 2 + (lane >> 4);
            LDMATRIX_X4(a_frag[mt], abase + row * ROWB + ch * 16);
        }
        uint32_t b_frag[4][4];
        #pragma unroll
        for (int nt2 = 0; nt2 < 4; ++nt2) {
            int n  = nt2 * 16 + ((lane >> 4) << 3) + (lane & 7);
            int ch = kc * 2 + ((lane >> 3) & 1);
            LDMATRIX_X4(b_frag[nt2], bbase + n * ROWB + ch * 16);
        }
        #pragma unroll
        for (int mt = 0; mt < 2; ++mt)
            #pragma unroll
            for (int nt = 0; nt < 8; ++nt)
                MMA16816(d[mt][nt], a_frag[mt],
                         b_frag[nt >> 1][(nt & 1) * 2],
                         b_frag[nt >> 1][(nt & 1) * 2 + 1]);
    }

    // ---- scatter-add straight from fragments; out rows fetched via shfl ----
    // fragment (mt, nt): rows r = mt*16+(lane>>2) (+8) within this warp;
    // 4 lanes with equal lane>>2 cover one contiguous 32B sector of one row.
    #pragma unroll
    for (int mt = 0; mt < 2; ++mt) {
        const int src  = mt * 16 + (lane >> 2);
        const int om0  = __shfl_sync(0xffffffffu, om, src);
        const int om1  = __shfl_sync(0xffffffffu, om, src + 8);
        float* dst0 = out + (size_t)om0 * C_OUT + (lane & 3) * 2;
        float* dst1 = out + (size_t)om1 * C_OUT + (lane & 3) * 2;
        #pragma unroll
        for (int nt = 0; nt < 8; ++nt) {
            if (om0 >= 0)
                asm volatile("red.global.add.v2.f32 [%0], {%1,%2};"
                             :: "l"(dst0 + nt * 8), "f"(d[mt][nt][0]), "f"(d[mt][nt][1])
                             : "memory");
            if (om1 >= 0)
                asm volatile("red.global.add.v2.f32 [%0], {%1,%2};"
                             :: "l"(dst1 + nt * 8), "f"(d[mt][nt][2]), "f"(d[mt][nt][3])
                             : "memory");
        }
    }
}

// ---------------- BN ---------------------------------------------------------
__global__ void zero_stats_kernel() {
    int t = threadIdx.x;
    if (t < C_OUT) { g_sum[t] = 0.f; g_sumsq[t] = 0.f; }
}

__global__ void __launch_bounds__(256)
stats_kernel(const float* __restrict__ out)
{
    __shared__ float ss[256], sq[256];
    const int t = threadIdx.x, ch = t & 63, rep = t >> 6;
    float s = 0.f, q = 0.f;
    #pragma unroll 4
    for (int row = blockIdx.x * 4 + rep; row < N_OUTP; row += gridDim.x * 4) {
        const float v = out[(size_t)row * C_OUT + ch];
        s += v; q = fmaf(v, v, q);
    }
    ss[t] = s; sq[t] = q;
    __syncthreads();
    if (t < 64) {
        atomicAdd(&g_sum[t],   ss[t] + ss[t + 64] + ss[t + 128] + ss[t + 192]);
        atomicAdd(&g_sumsq[t], sq[t] + sq[t + 64] + sq[t + 128] + sq[t + 192]);
    }
}

__global__ void finalize_kernel(const float* __restrict__ gamma,
                                const float* __restrict__ beta)
{
    const int c = threadIdx.x;
    if (c < C_OUT) {
        const float inv_n = 1.0f / (float)N_OUTP;
        const float mean = g_sum[c] * inv_n;
        const float var  = g_sumsq[c] * inv_n - mean * mean;
        const float sc   = gamma[c] * rsqrtf(var + BN_EPS);
        g_scale[c] = sc;
        g_bias[c]  = beta[c] - mean * sc;
    }
}

__global__ void __launch_bounds__(256)
normalize_kernel(float* __restrict__ out)
{
    __shared__ float sc[C_OUT], bs[C_OUT];
    if (threadIdx.x < C_OUT) {
        sc[threadIdx.x] = g_scale[threadIdx.x];
        bs[threadIdx.x] = g_bias[threadIdx.x];
    }
    __syncthreads();
    const int total4 = N_OUTP * C_OUT / 4;
    for (int i = blockIdx.x * blockDim.x + threadIdx.x; i < total4;
         i += gridDim.x * blockDim.x) {
        float4 v = ((float4*)out)[i];
        const int c0 = (i * 4) & 63;
        v.x = fmaxf(fmaf(v.x, sc[c0 + 0], bs[c0 + 0]), 0.f);
        v.y = fmaxf(fmaf(v.y, sc[c0 + 1], bs[c0 + 1]), 0.f);
        v.z = fmaxf(fmaf(v.z, sc[c0 + 2], bs[c0 + 2]), 0.f);
        v.w = fmaxf(fmaf(v.w, sc[c0 + 3], bs[c0 + 3]), 0.f);
        ((float4*)out)[i] = v;
    }
}

// ---------------- launch ----------------------------------------------------
extern "C" void kernel_launch(void* const* d_in, const int* in_sizes, int n_in,
                              void* d_out, int out_size)
{
    const float* x       = (const float*)d_in[0];
    const float* weight  = (const float*)d_in[1];
    const float* gamma   = (const float*)d_in[2];
    const float* beta    = (const float*)d_in[3];
    const int*   in_map  = (const int*)d_in[4];
    const int*   out_map = (const int*)d_in[5];
    float*       out     = (float*)d_out;

    cudaFuncSetAttribute(fused_kernel, cudaFuncAttributeMaxDynamicSharedMemorySize,
                         SMEM_FUSED);

    cudaMemsetAsync(out, 0, (size_t)out_size * sizeof(float));
    zero_stats_kernel<<<1, 128>>>();

    conv_x_kernel<<<(N_ROWS * 32 + 255) / 256, 256>>>(x);
    conv_w_kernel<<<(KOFF * C_IN * C_OUT + 255) / 256, 256>>>(weight);

    {
        dim3 grid((M_PAIRS + PAIRS_BLK - 1) / PAIRS_BLK, KOFF);
        fused_kernel<<<grid, PAIRS_BLK, SMEM_FUSED>>>(in_map, out_map, out);
    }

    stats_kernel<<<1184, 256>>>(out);
    finalize_kernel<<<1, 64>>>(gamma, beta);
    normalize_kernel<<<2048, 256>>>(out);
}